// round 12
// baseline (speedup 1.0000x reference)
#include <cuda_runtime.h>
#include <cuda_bf16.h>
#include <math.h>

// ---------------------------------------------------------------------------
// HybridConv: out[n] = MLP(RBF(sigmoid(dot(data[n], conv_w) + conv_b)))
// out = f(t), t = 2*sigmoid(logit)-1 = tanh(logit/2), f analytic on [-1,1].
// SINGLE LAUNCH. Per-warp register prologue (~0.2us, fully parallel, no
// syncthreads): f at 32 Chebyshev nodes via fast approx math -> shuffle DCT
// -> monomial coefficients via compile-time integer T_k matrix -> broadcast.
// Main loop (unchanged from proven R11): warp-blocked 128-patch chunks,
// 512B-contiguous LDG.128, coalesced STG.32, degree-11 Horner in fma.rn.f32x2.
// ---------------------------------------------------------------------------

#define NCOEF 12   // monomial degree 11
#define BASIS 8
#define HIDDEN 16

// Chebyshev T_k power-basis coefficients (exact integers), T[k][j] = coeff of x^j
__device__ __constant__ float c_T[NCOEF][NCOEF] = {
    {   1,    0,    0,    0,     0,     0,    0,    0,     0,     0,    0,    0},
    {   0,    1,    0,    0,     0,     0,    0,    0,     0,     0,    0,    0},
    {  -1,    0,    2,    0,     0,     0,    0,    0,     0,     0,    0,    0},
    {   0,   -3,    0,    4,     0,     0,    0,    0,     0,     0,    0,    0},
    {   1,    0,   -8,    0,     8,     0,    0,    0,     0,     0,    0,    0},
    {   0,    5,    0,  -20,     0,    16,    0,    0,     0,     0,    0,    0},
    {  -1,    0,   18,    0,   -48,     0,   32,    0,     0,     0,    0,    0},
    {   0,   -7,    0,   56,     0,  -112,    0,   64,     0,     0,    0,    0},
    {   1,    0,  -32,    0,   160,     0, -256,    0,   128,     0,    0,    0},
    {   0,    9,    0, -120,     0,   432,    0, -576,     0,   256,    0,    0},
    {  -1,    0,   50,    0,  -400,     0, 1120,    0, -1280,     0,  512,    0},
    {   0,  -11,    0,  220,     0, -1232,    0, 2816,     0, -2816,    0, 1024}
};

#define FMA2(d, a, b, c) \
    asm("fma.rn.f32x2 %0, %1, %2, %3;" \
        : "=l"(d) : "l"(a), "l"(b), "l"(c))
#define PACK2(d, lo, hi) \
    asm("mov.b64 %0, {%1, %2};" : "=l"(d) : "f"(lo), "f"(hi))
#define UNPACK2(lo, hi, s) \
    asm("mov.b64 {%0, %1}, %2;" : "=f"(lo), "=f"(hi) : "l"(s))

__device__ __forceinline__ float fast_tanh(float x) {
    float y;
    asm("tanh.approx.f32 %0, %1;" : "=f"(y) : "f"(x));
    return y;
}

// ---- single fused kernel --------------------------------------------------
__global__ void __launch_bounds__(256, 6)
hybridconv_kernel(const float4* __restrict__ data,
                  const float* __restrict__ conv_w,
                  const float* __restrict__ conv_b,
                  const float* __restrict__ basis,
                  const float* __restrict__ w1v,
                  const float* __restrict__ b1v,
                  const float* __restrict__ w2v,
                  const float* __restrict__ b2v,
                  float* __restrict__ out, int nChunks, int n) {
    const int gid    = blockIdx.x * blockDim.x + threadIdx.x;
    const int lane   = threadIdx.x & 31;
    const int warpId = gid >> 5;
    const int nWarps = (gridDim.x * blockDim.x) >> 5;

    // ---- per-warp prologue: coefficients in registers, fast approx math ---
    // node: t_j = cos(pi*(2j+1)/64), act a = (1+t)/2   (lane = node j)
    float t_node = cospif((float)(2 * lane + 1) * (1.0f / 64.0f));
    float a = 0.5f + 0.5f * t_node;

    float fv;
    {
        float feats[BASIS];
#pragma unroll
        for (int j = 0; j < BASIS; j++) {
            float s = 0.0f;
#pragma unroll
            for (int k = 0; k < 4; k++) {
                float d = a - basis[j * 4 + k];
                s = fmaf(d, d, s);
            }
            feats[j] = __expf(-s);           // GAMMA = 1, fast exp
        }
        fv = b2v[0];
#pragma unroll
        for (int i = 0; i < HIDDEN; i++) {
            float p = b1v[i];
#pragma unroll
            for (int j = 0; j < BASIS; j++)
                p = fmaf(feats[j], w1v[j * HIDDEN + i], p);
            fv = fmaf(fast_tanh(p), w2v[i], fv);
        }
    }

    // DCT: e_k = (1/16) sum_j f_j cos(pi*k*(2j+1)/64); lane = k. Full warp.
    float ek = 0.0f;
#pragma unroll 4
    for (int j = 0; j < 32; j++) {
        float fj = __shfl_sync(0xFFFFFFFFu, fv, j);
        float w  = cospif((float)(lane * (2 * j + 1)) * (1.0f / 64.0f));
        ek = fmaf(fj, w, ek);
    }
    ek *= (1.0f / 16.0f);
    if (lane == 0) ek *= 0.5f;               // e_0 = c_0/2

    // monomial a_j = sum_k e_k * T[k][j] (lane = j); all lanes shuffle
    float aj = 0.0f;
#pragma unroll
    for (int k = 0; k < NCOEF; k++) {
        float e = __shfl_sync(0xFFFFFFFFu, ek, k);
        aj = fmaf(e, c_T[k][lane < NCOEF ? lane : 0], aj);
    }

    // broadcast final coefficients to all lanes, pack pairs once
    unsigned long long c2[NCOEF];
    float cs[NCOEF];
#pragma unroll
    for (int k = 0; k < NCOEF; k++) {
        float ck = __shfl_sync(0xFFFFFFFFu, aj, k);
        cs[k] = ck;
        PACK2(c2[k], ck, ck);
    }

    const float w0 = conv_w[0], w1 = conv_w[1];
    const float w2 = conv_w[2], w3 = conv_w[3];
    const float bb = conv_b[0];

    // ---- main loop: warp-blocked, fully coalesced -------------------------
    for (int chunk = warpId; chunk < nChunks; chunk += nWarps) {
        const int base = (chunk << 7) + lane;
        const float4* p = data + base;
        float4 v0 = __ldcs(p);
        float l0 = fmaf(v0.x, w0, fmaf(v0.y, w1, fmaf(v0.z, w2, fmaf(v0.w, w3, bb))));
        float4 v1 = __ldcs(p + 32);
        float l1 = fmaf(v1.x, w0, fmaf(v1.y, w1, fmaf(v1.z, w2, fmaf(v1.w, w3, bb))));
        float4 v2 = __ldcs(p + 64);
        float l2 = fmaf(v2.x, w0, fmaf(v2.y, w1, fmaf(v2.z, w2, fmaf(v2.w, w3, bb))));
        float4 v3 = __ldcs(p + 96);
        float l3 = fmaf(v3.x, w0, fmaf(v3.y, w1, fmaf(v3.z, w2, fmaf(v3.w, w3, bb))));

        // t = 2*sigmoid(l)-1 = tanh(l/2): one MUFU each
        float t0 = fast_tanh(0.5f * l0);
        float t1 = fast_tanh(0.5f * l1);
        float t2 = fast_tanh(0.5f * l2);
        float t3 = fast_tanh(0.5f * l3);

        unsigned long long tA, tB;
        PACK2(tA, t0, t1);
        PACK2(tB, t2, t3);

        // Horner, two f32x2 chains: 1 FMA2 per level per pair
        unsigned long long hA = c2[NCOEF - 1], hB = c2[NCOEF - 1];
#pragma unroll
        for (int k = NCOEF - 2; k >= 0; k--) {
            FMA2(hA, tA, hA, c2[k]);
            FMA2(hB, tB, hB, c2[k]);
        }

        float r0, r1, r2, r3;
        UNPACK2(r0, r1, hA);
        UNPACK2(r2, r3, hB);
        float* o = out + base;
        __stcs(o,      r0);
        __stcs(o + 32, r1);
        __stcs(o + 64, r2);
        __stcs(o + 96, r3);
    }

    // defensive tail for n % 128 != 0 (empty for N = 2^23)
    for (int k = (nChunks << 7) + gid; k < n; k += gridDim.x * blockDim.x) {
        float4 v = data[k];
        float l = fmaf(v.x, w0, fmaf(v.y, w1, fmaf(v.z, w2, fmaf(v.w, w3, bb))));
        float t = fast_tanh(0.5f * l);
        float h = cs[NCOEF - 1];
        for (int q = NCOEF - 2; q >= 0; q--)
            h = fmaf(t, h, cs[q]);
        out[k] = h;
    }
}

extern "C" void kernel_launch(void* const* d_in, const int* in_sizes, int n_in,
                              void* d_out, int out_size) {
    const float* data   = (const float*)d_in[0];   // [N, 2, 2]
    const float* conv_w = (const float*)d_in[1];   // [2, 2]
    const float* conv_b = (const float*)d_in[2];   // [1]
    const float* basis  = (const float*)d_in[3];   // [8, 4]
    const float* w1     = (const float*)d_in[4];   // [8, 16]
    const float* b1     = (const float*)d_in[5];   // [16]
    const float* w2     = (const float*)d_in[6];   // [16, 1]
    const float* b2     = (const float*)d_in[7];   // [1]

    const int n       = in_sizes[0] / 4;   // patches
    const int nChunks = n >> 7;            // 128-patch warp chunks

    // single launch: 912 blocks = exactly 6 CTAs/SM x 152 SMs
    hybridconv_kernel<<<912, 256>>>(
        (const float4*)data, conv_w, conv_b, basis, w1, b1, w2, b2,
        (float*)d_out, nChunks, n);
}

// round 13
// speedup vs baseline: 1.1721x; 1.1721x over previous
#include <cuda_runtime.h>
#include <cuda_bf16.h>
#include <math.h>

// ---------------------------------------------------------------------------
// HybridConv: out[n] = MLP(RBF(sigmoid(dot(data[n], conv_w) + conv_b)))
// out = f(t), t = 2*sigmoid(logit)-1 = tanh(logit/2), f analytic on [-1,1].
// SINGLE LAUNCH with a COOPERATIVE BLOCK PROLOGUE (~300 warp-instrs/block):
//   - all 256 threads precompute 4 DCT weights each (1024 total, parallel)
//   - warp 0 concurrently evaluates f at 32 Chebyshev nodes (fast math)
//   - one sync; 4-term partial dots; warp 0 reduces + converts to monomial
//     via compile-time integer T_k matrix; 12 coeffs to smem; sync.
// Main loop (proven R11): warp-blocked 128-patch chunks, 512B-contiguous
// LDG.128, coalesced STG.32, degree-11 Horner in fma.rn.f32x2.
// ---------------------------------------------------------------------------

#define NCOEF 12   // monomial degree 11
#define BASIS 8
#define HIDDEN 16

// Chebyshev T_k power-basis coefficients (exact integers), T[k][j] = coeff of x^j
__device__ __constant__ float c_T[NCOEF][NCOEF] = {
    {   1,    0,    0,    0,     0,     0,    0,    0,     0,     0,    0,    0},
    {   0,    1,    0,    0,     0,     0,    0,    0,     0,     0,    0,    0},
    {  -1,    0,    2,    0,     0,     0,    0,    0,     0,     0,    0,    0},
    {   0,   -3,    0,    4,     0,     0,    0,    0,     0,     0,    0,    0},
    {   1,    0,   -8,    0,     8,     0,    0,    0,     0,     0,    0,    0},
    {   0,    5,    0,  -20,     0,    16,    0,    0,     0,     0,    0,    0},
    {  -1,    0,   18,    0,   -48,     0,   32,    0,     0,     0,    0,    0},
    {   0,   -7,    0,   56,     0,  -112,    0,   64,     0,     0,    0,    0},
    {   1,    0,  -32,    0,   160,     0, -256,    0,   128,     0,    0,    0},
    {   0,    9,    0, -120,     0,   432,    0, -576,     0,   256,    0,    0},
    {  -1,    0,   50,    0,  -400,     0, 1120,    0, -1280,     0,  512,    0},
    {   0,  -11,    0,  220,     0, -1232,    0, 2816,     0, -2816,    0, 1024}
};

#define FMA2(d, a, b, c) \
    asm("fma.rn.f32x2 %0, %1, %2, %3;" \
        : "=l"(d) : "l"(a), "l"(b), "l"(c))
#define PACK2(d, lo, hi) \
    asm("mov.b64 %0, {%1, %2};" : "=l"(d) : "f"(lo), "f"(hi))
#define UNPACK2(lo, hi, s) \
    asm("mov.b64 {%0, %1}, %2;" : "=f"(lo), "=f"(hi) : "l"(s))

__device__ __forceinline__ float fast_tanh(float x) {
    float y;
    asm("tanh.approx.f32 %0, %1;" : "=f"(y) : "f"(x));
    return y;
}

// ---- single fused kernel --------------------------------------------------
__global__ void __launch_bounds__(256, 6)
hybridconv_kernel(const float4* __restrict__ data,
                  const float* __restrict__ conv_w,
                  const float* __restrict__ conv_b,
                  const float* __restrict__ basis,
                  const float* __restrict__ w1v,
                  const float* __restrict__ b1v,
                  const float* __restrict__ w2v,
                  const float* __restrict__ b2v,
                  float* __restrict__ out, int nChunks, int n) {
    __shared__ float s_f[32];          // f at 32 Chebyshev nodes
    __shared__ float s_part[32][9];    // DCT partials, padded (stride 9)
    __shared__ float s_c[NCOEF];       // final monomial coefficients

    const int tid  = threadIdx.x;
    const int lane = tid & 31;
    const int kk   = tid >> 3;         // coefficient index 0..31
    const int gg   = tid & 7;          // j-group 0..7

    // ---- prologue phase 1 (parallel): DCT weights + node evals ------------
    // Every thread: its 4 cosine weights w_kj = cos(pi*k*(2j+1)/64)
    float wdct[4];
#pragma unroll
    for (int u = 0; u < 4; u++) {
        int j = gg * 4 + u;
        wdct[u] = cospif((float)(kk * (2 * j + 1)) * (1.0f / 64.0f));
    }
    // Warp 0 concurrently: f at node lane (fast approx math)
    if (tid < 32) {
        float t_node = cospif((float)(2 * lane + 1) * (1.0f / 64.0f));
        float a = 0.5f + 0.5f * t_node;
        float feats[BASIS];
#pragma unroll
        for (int j = 0; j < BASIS; j++) {
            float s = 0.0f;
#pragma unroll
            for (int k = 0; k < 4; k++) {
                float d = a - basis[j * 4 + k];
                s = fmaf(d, d, s);
            }
            feats[j] = __expf(-s);           // GAMMA = 1
        }
        float fv = b2v[0];
#pragma unroll
        for (int i = 0; i < HIDDEN; i++) {
            float p = b1v[i];
#pragma unroll
            for (int j = 0; j < BASIS; j++)
                p = fmaf(feats[j], w1v[j * HIDDEN + i], p);
            fv = fmaf(fast_tanh(p), w2v[i], fv);
        }
        s_f[tid] = fv;
    }
    __syncthreads();

    // ---- prologue phase 2: partial DCT dots (4 terms per thread) ----------
    {
        float part = 0.0f;
#pragma unroll
        for (int u = 0; u < 4; u++)
            part = fmaf(s_f[gg * 4 + u], wdct[u], part);
        s_part[kk][gg] = part;
    }
    __syncthreads();

    // ---- prologue phase 3: warp 0 reduces, converts to monomial -----------
    if (tid < 32) {
        float e = 0.0f;
#pragma unroll
        for (int g = 0; g < 8; g++) e += s_part[lane][g];
        e *= (1.0f / 16.0f);
        if (lane == 0) e *= 0.5f;            // e_0 = c_0/2
        // monomial a_j = sum_k e_k * T[k][j] (lane = j); all lanes shuffle
        float aj = 0.0f;
#pragma unroll
        for (int k = 0; k < NCOEF; k++) {
            float ek = __shfl_sync(0xFFFFFFFFu, e, k);
            aj = fmaf(ek, c_T[k][lane < NCOEF ? lane : 0], aj);
        }
        if (lane < NCOEF) s_c[lane] = aj;
    }
    __syncthreads();

    // coefficients to registers, pairs packed once
    unsigned long long c2[NCOEF];
    float cs[NCOEF];
#pragma unroll
    for (int k = 0; k < NCOEF; k++) {
        float ck = s_c[k];
        cs[k] = ck;
        PACK2(c2[k], ck, ck);
    }

    const float w0 = conv_w[0], w1 = conv_w[1];
    const float w2 = conv_w[2], w3 = conv_w[3];
    const float bb = conv_b[0];

    const int gid    = blockIdx.x * blockDim.x + threadIdx.x;
    const int warpId = gid >> 5;
    const int nWarps = (gridDim.x * blockDim.x) >> 5;

    // ---- main loop: warp-blocked, fully coalesced (proven R11) ------------
    for (int chunk = warpId; chunk < nChunks; chunk += nWarps) {
        const int base = (chunk << 7) + lane;
        const float4* p = data + base;
        float4 v0 = __ldcs(p);
        float l0 = fmaf(v0.x, w0, fmaf(v0.y, w1, fmaf(v0.z, w2, fmaf(v0.w, w3, bb))));
        float4 v1 = __ldcs(p + 32);
        float l1 = fmaf(v1.x, w0, fmaf(v1.y, w1, fmaf(v1.z, w2, fmaf(v1.w, w3, bb))));
        float4 v2 = __ldcs(p + 64);
        float l2 = fmaf(v2.x, w0, fmaf(v2.y, w1, fmaf(v2.z, w2, fmaf(v2.w, w3, bb))));
        float4 v3 = __ldcs(p + 96);
        float l3 = fmaf(v3.x, w0, fmaf(v3.y, w1, fmaf(v3.z, w2, fmaf(v3.w, w3, bb))));

        // t = 2*sigmoid(l)-1 = tanh(l/2): one MUFU each
        float t0 = fast_tanh(0.5f * l0);
        float t1 = fast_tanh(0.5f * l1);
        float t2 = fast_tanh(0.5f * l2);
        float t3 = fast_tanh(0.5f * l3);

        unsigned long long tA, tB;
        PACK2(tA, t0, t1);
        PACK2(tB, t2, t3);

        // Horner, two f32x2 chains: 1 FMA2 per level per pair
        unsigned long long hA = c2[NCOEF - 1], hB = c2[NCOEF - 1];
#pragma unroll
        for (int k = NCOEF - 2; k >= 0; k--) {
            FMA2(hA, tA, hA, c2[k]);
            FMA2(hB, tB, hB, c2[k]);
        }

        float r0, r1, r2, r3;
        UNPACK2(r0, r1, hA);
        UNPACK2(r2, r3, hB);
        float* o = out + base;
        __stcs(o,      r0);
        __stcs(o + 32, r1);
        __stcs(o + 64, r2);
        __stcs(o + 96, r3);
    }

    // defensive tail for n % 128 != 0 (empty for N = 2^23)
    for (int k = (nChunks << 7) + gid; k < n; k += gridDim.x * blockDim.x) {
        float4 v = data[k];
        float l = fmaf(v.x, w0, fmaf(v.y, w1, fmaf(v.z, w2, fmaf(v.w, w3, bb))));
        float t = fast_tanh(0.5f * l);
        float h = cs[NCOEF - 1];
#pragma unroll
        for (int q = NCOEF - 2; q >= 0; q--)
            h = fmaf(t, h, cs[q]);
        out[k] = h;
    }
}

extern "C" void kernel_launch(void* const* d_in, const int* in_sizes, int n_in,
                              void* d_out, int out_size) {
    const float* data   = (const float*)d_in[0];   // [N, 2, 2]
    const float* conv_w = (const float*)d_in[1];   // [2, 2]
    const float* conv_b = (const float*)d_in[2];   // [1]
    const float* basis  = (const float*)d_in[3];   // [8, 4]
    const float* w1     = (const float*)d_in[4];   // [8, 16]
    const float* b1     = (const float*)d_in[5];   // [16]
    const float* w2     = (const float*)d_in[6];   // [16, 1]
    const float* b2     = (const float*)d_in[7];   // [1]

    const int n       = in_sizes[0] / 4;   // patches
    const int nChunks = n >> 7;            // 128-patch warp chunks

    // single launch: 912 blocks = exactly 6 CTAs/SM x 152 SMs
    hybridconv_kernel<<<912, 256>>>(
        (const float4*)data, conv_w, conv_b, basis, w1, b1, w2, b2,
        (float*)d_out, nChunks, n);
}

// round 14
// speedup vs baseline: 1.3279x; 1.1329x over previous
#include <cuda_runtime.h>
#include <cuda_bf16.h>
#include <math.h>

// ---------------------------------------------------------------------------
// HybridConv: out[n] = MLP(RBF(sigmoid(dot(data[n], conv_w) + conv_b)))
// out = f(t), t = 2*sigmoid(logit)-1 = tanh(logit/2), f analytic on [-1,1].
// SINGLE LAUNCH, FULLY-PARALLEL block prologue:
//   - 256 threads: thread (node, g) computes node's RBF feats + 2 hidden
//     units; 8-lane shfl reduce -> f at 32 Chebyshev nodes (w1 loads spread
//     16/thread; critical path ~2 tanh deep, not 16)
//   - DCT partial dots (4 terms/thread) -> warp-0 reduce -> monomial coeffs
//     via compile-time integer T_k matrix.
// Main loop (proven R11): warp-blocked 128-patch chunks, 512B-contiguous
// LDG.128, coalesced STG.32, degree-11 Horner in fma.rn.f32x2.
// ---------------------------------------------------------------------------

#define NCOEF 12   // monomial degree 11
#define BASIS 8
#define HIDDEN 16

// Chebyshev T_k power-basis coefficients (exact integers), T[k][j] = coeff of x^j
__device__ __constant__ float c_T[NCOEF][NCOEF] = {
    {   1,    0,    0,    0,     0,     0,    0,    0,     0,     0,    0,    0},
    {   0,    1,    0,    0,     0,     0,    0,    0,     0,     0,    0,    0},
    {  -1,    0,    2,    0,     0,     0,    0,    0,     0,     0,    0,    0},
    {   0,   -3,    0,    4,     0,     0,    0,    0,     0,     0,    0,    0},
    {   1,    0,   -8,    0,     8,     0,    0,    0,     0,     0,    0,    0},
    {   0,    5,    0,  -20,     0,    16,    0,    0,     0,     0,    0,    0},
    {  -1,    0,   18,    0,   -48,     0,   32,    0,     0,     0,    0,    0},
    {   0,   -7,    0,   56,     0,  -112,    0,   64,     0,     0,    0,    0},
    {   1,    0,  -32,    0,   160,     0, -256,    0,   128,     0,    0,    0},
    {   0,    9,    0, -120,     0,   432,    0, -576,     0,   256,    0,    0},
    {  -1,    0,   50,    0,  -400,     0, 1120,    0, -1280,     0,  512,    0},
    {   0,  -11,    0,  220,     0, -1232,    0, 2816,     0, -2816,    0, 1024}
};

#define FMA2(d, a, b, c) \
    asm("fma.rn.f32x2 %0, %1, %2, %3;" \
        : "=l"(d) : "l"(a), "l"(b), "l"(c))
#define PACK2(d, lo, hi) \
    asm("mov.b64 %0, {%1, %2};" : "=l"(d) : "f"(lo), "f"(hi))
#define UNPACK2(lo, hi, s) \
    asm("mov.b64 {%0, %1}, %2;" : "=f"(lo), "=f"(hi) : "l"(s))

__device__ __forceinline__ float fast_tanh(float x) {
    float y;
    asm("tanh.approx.f32 %0, %1;" : "=f"(y) : "f"(x));
    return y;
}

// ---- single fused kernel --------------------------------------------------
__global__ void __launch_bounds__(256, 6)
hybridconv_kernel(const float4* __restrict__ data,
                  const float* __restrict__ conv_w,
                  const float* __restrict__ conv_b,
                  const float* __restrict__ basis,
                  const float* __restrict__ w1v,
                  const float* __restrict__ b1v,
                  const float* __restrict__ w2v,
                  const float* __restrict__ b2v,
                  float* __restrict__ out, int nChunks, int n) {
    __shared__ float s_f[32];          // f at 32 Chebyshev nodes
    __shared__ float s_part[32][9];    // DCT partials, padded (stride 9)
    __shared__ float s_c[NCOEF];       // final monomial coefficients

    const int tid  = threadIdx.x;
    const int lane = tid & 31;

    // ---- prologue phase 1: f at 32 nodes, ALL 256 threads -----------------
    // thread (node = tid>>3, g = tid&7) computes hidden units g and g+8.
    {
        const int node = tid >> 3;
        const int g    = tid & 7;

        float t_node = cospif((float)(2 * node + 1) * (1.0f / 64.0f));
        float a = 0.5f + 0.5f * t_node;

        float feats[BASIS];
#pragma unroll
        for (int j = 0; j < BASIS; j++) {
            float s = 0.0f;
#pragma unroll
            for (int k = 0; k < 4; k++) {
                float d = a - basis[j * 4 + k];
                s = fmaf(d, d, s);
            }
            feats[j] = __expf(-s);           // GAMMA = 1
        }
        float v = 0.0f;
#pragma unroll
        for (int u = 0; u < 2; u++) {
            int h = g + u * 8;
            float p = b1v[h];
#pragma unroll
            for (int j = 0; j < BASIS; j++)
                p = fmaf(feats[j], w1v[j * HIDDEN + h], p);
            v = fmaf(fast_tanh(p), w2v[h], v);
        }
        // reduce over the 8 threads of this node (contiguous 8-lane groups;
        // every lane of the warp participates in every shuffle)
#pragma unroll
        for (int off = 4; off; off >>= 1)
            v += __shfl_xor_sync(0xFFFFFFFFu, v, off);
        if (g == 0) s_f[node] = v + b2v[0];
    }

    // DCT weights (independent, before sync): thread (kk = tid>>3, gg = tid&7)
    const int kk = tid >> 3;           // coefficient index 0..31
    const int gg = tid & 7;            // j-group 0..7
    float wdct[4];
#pragma unroll
    for (int u = 0; u < 4; u++) {
        int j = gg * 4 + u;
        wdct[u] = cospif((float)(kk * (2 * j + 1)) * (1.0f / 64.0f));
    }
    __syncthreads();

    // ---- prologue phase 2: partial DCT dots (4 terms per thread) ----------
    {
        float part = 0.0f;
#pragma unroll
        for (int u = 0; u < 4; u++)
            part = fmaf(s_f[gg * 4 + u], wdct[u], part);
        s_part[kk][gg] = part;
    }
    __syncthreads();

    // ---- prologue phase 3: warp 0 reduces, converts to monomial -----------
    if (tid < 32) {
        float e = 0.0f;
#pragma unroll
        for (int g2 = 0; g2 < 8; g2++) e += s_part[lane][g2];
        e *= (1.0f / 16.0f);
        if (lane == 0) e *= 0.5f;            // e_0 = c_0/2
        // monomial a_j = sum_k e_k * T[k][j] (lane = j); all lanes shuffle
        float aj = 0.0f;
#pragma unroll
        for (int k = 0; k < NCOEF; k++) {
            float ek = __shfl_sync(0xFFFFFFFFu, e, k);
            aj = fmaf(ek, c_T[k][lane < NCOEF ? lane : 0], aj);
        }
        if (lane < NCOEF) s_c[lane] = aj;
    }
    __syncthreads();

    // coefficients to registers, pairs packed once
    unsigned long long c2[NCOEF];
#pragma unroll
    for (int k = 0; k < NCOEF; k++) {
        float ck = s_c[k];
        PACK2(c2[k], ck, ck);
    }

    const float w0 = conv_w[0], w1 = conv_w[1];
    const float w2 = conv_w[2], w3 = conv_w[3];
    const float bb = conv_b[0];

    const int gid    = blockIdx.x * blockDim.x + threadIdx.x;
    const int warpId = gid >> 5;
    const int nWarps = (gridDim.x * blockDim.x) >> 5;

    // ---- main loop: warp-blocked, fully coalesced (proven R11) ------------
    for (int chunk = warpId; chunk < nChunks; chunk += nWarps) {
        const int base = (chunk << 7) + lane;
        const float4* p = data + base;
        float4 v0 = __ldcs(p);
        float l0 = fmaf(v0.x, w0, fmaf(v0.y, w1, fmaf(v0.z, w2, fmaf(v0.w, w3, bb))));
        float4 v1 = __ldcs(p + 32);
        float l1 = fmaf(v1.x, w0, fmaf(v1.y, w1, fmaf(v1.z, w2, fmaf(v1.w, w3, bb))));
        float4 v2 = __ldcs(p + 64);
        float l2 = fmaf(v2.x, w0, fmaf(v2.y, w1, fmaf(v2.z, w2, fmaf(v2.w, w3, bb))));
        float4 v3 = __ldcs(p + 96);
        float l3 = fmaf(v3.x, w0, fmaf(v3.y, w1, fmaf(v3.z, w2, fmaf(v3.w, w3, bb))));

        // t = 2*sigmoid(l)-1 = tanh(l/2): one MUFU each
        float t0 = fast_tanh(0.5f * l0);
        float t1 = fast_tanh(0.5f * l1);
        float t2 = fast_tanh(0.5f * l2);
        float t3 = fast_tanh(0.5f * l3);

        unsigned long long tA, tB;
        PACK2(tA, t0, t1);
        PACK2(tB, t2, t3);

        // Horner, two f32x2 chains: 1 FMA2 per level per pair
        unsigned long long hA = c2[NCOEF - 1], hB = c2[NCOEF - 1];
#pragma unroll
        for (int k = NCOEF - 2; k >= 0; k--) {
            FMA2(hA, tA, hA, c2[k]);
            FMA2(hB, tB, hB, c2[k]);
        }

        float r0, r1, r2, r3;
        UNPACK2(r0, r1, hA);
        UNPACK2(r2, r3, hB);
        float* o = out + base;
        __stcs(o,      r0);
        __stcs(o + 32, r1);
        __stcs(o + 64, r2);
        __stcs(o + 96, r3);
    }

    // defensive tail for n % 128 != 0 (empty for N = 2^23); coeffs from c2
    for (int k = (nChunks << 7) + gid; k < n; k += gridDim.x * blockDim.x) {
        float4 v = data[k];
        float l = fmaf(v.x, w0, fmaf(v.y, w1, fmaf(v.z, w2, fmaf(v.w, w3, bb))));
        float t = fast_tanh(0.5f * l);
        float hi_, ck_;
        UNPACK2(ck_, hi_, c2[NCOEF - 1]);
        float h = ck_;
#pragma unroll
        for (int q = NCOEF - 2; q >= 0; q--) {
            UNPACK2(ck_, hi_, c2[q]);
            h = fmaf(t, h, ck_);
        }
        out[k] = h;
    }
}

extern "C" void kernel_launch(void* const* d_in, const int* in_sizes, int n_in,
                              void* d_out, int out_size) {
    const float* data   = (const float*)d_in[0];   // [N, 2, 2]
    const float* conv_w = (const float*)d_in[1];   // [2, 2]
    const float* conv_b = (const float*)d_in[2];   // [1]
    const float* basis  = (const float*)d_in[3];   // [8, 4]
    const float* w1     = (const float*)d_in[4];   // [8, 16]
    const float* b1     = (const float*)d_in[5];   // [16]
    const float* w2     = (const float*)d_in[6];   // [16, 1]
    const float* b2     = (const float*)d_in[7];   // [1]

    const int n       = in_sizes[0] / 4;   // patches
    const int nChunks = n >> 7;            // 128-patch warp chunks

    // single launch: 912 blocks = exactly 6 CTAs/SM x 152 SMs
    hybridconv_kernel<<<912, 256>>>(
        (const float4*)data, conv_w, conv_b, basis, w1, b1, w2, b2,
        (float*)d_out, nChunks, n);
}

// round 15
// speedup vs baseline: 1.3366x; 1.0066x over previous
#include <cuda_runtime.h>
#include <cuda_bf16.h>
#include <math.h>

// ---------------------------------------------------------------------------
// HybridConv: out[n] = MLP(RBF(sigmoid(dot(data[n], conv_w) + conv_b)))
// out = f(t), t = 2*sigmoid(logit)-1 = tanh(logit/2), f analytic on [-1,1].
// SINGLE LAUNCH, SOFTWARE-PIPELINED:
//   - first chunk's LDG.128s issue BEFORE the block prologue (prologue
//     compute runs under the load latency)
//   - fully-parallel prologue (256 threads): f at 32 Chebyshev nodes ->
//     DCT -> monomial coeffs via compile-time integer T_k matrix
//   - steady state: consume v->t, then issue NEXT chunk's loads before the
//     Horner chain + stores of the current chunk (loads always in flight)
// Warp-blocked 128-patch chunks, 512B-contiguous LDG.128, coalesced STG.32,
// degree-11 Horner in fma.rn.f32x2 (coeff pair packed once per k, shared by
// both chains).
// ---------------------------------------------------------------------------

#define NCOEF 12   // monomial degree 11
#define BASIS 8
#define HIDDEN 16

// Chebyshev T_k power-basis coefficients (exact integers), T[k][j] = coeff of x^j
__device__ __constant__ float c_T[NCOEF][NCOEF] = {
    {   1,    0,    0,    0,     0,     0,    0,    0,     0,     0,    0,    0},
    {   0,    1,    0,    0,     0,     0,    0,    0,     0,     0,    0,    0},
    {  -1,    0,    2,    0,     0,     0,    0,    0,     0,     0,    0,    0},
    {   0,   -3,    0,    4,     0,     0,    0,    0,     0,     0,    0,    0},
    {   1,    0,   -8,    0,     8,     0,    0,    0,     0,     0,    0,    0},
    {   0,    5,    0,  -20,     0,    16,    0,    0,     0,     0,    0,    0},
    {  -1,    0,   18,    0,   -48,     0,   32,    0,     0,     0,    0,    0},
    {   0,   -7,    0,   56,     0,  -112,    0,   64,     0,     0,    0,    0},
    {   1,    0,  -32,    0,   160,     0, -256,    0,   128,     0,    0,    0},
    {   0,    9,    0, -120,     0,   432,    0, -576,     0,   256,    0,    0},
    {  -1,    0,   50,    0,  -400,     0, 1120,    0, -1280,     0,  512,    0},
    {   0,  -11,    0,  220,     0, -1232,    0, 2816,     0, -2816,    0, 1024}
};

#define FMA2(d, a, b, c) \
    asm("fma.rn.f32x2 %0, %1, %2, %3;" \
        : "=l"(d) : "l"(a), "l"(b), "l"(c))
#define PACK2(d, lo, hi) \
    asm("mov.b64 %0, {%1, %2};" : "=l"(d) : "f"(lo), "f"(hi))
#define UNPACK2(lo, hi, s) \
    asm("mov.b64 {%0, %1}, %2;" : "=f"(lo), "=f"(hi) : "l"(s))

__device__ __forceinline__ float fast_tanh(float x) {
    float y;
    asm("tanh.approx.f32 %0, %1;" : "=f"(y) : "f"(x));
    return y;
}

// ---- single fused kernel --------------------------------------------------
__global__ void __launch_bounds__(256, 6)
hybridconv_kernel(const float4* __restrict__ data,
                  const float* __restrict__ conv_w,
                  const float* __restrict__ conv_b,
                  const float* __restrict__ basis,
                  const float* __restrict__ w1v,
                  const float* __restrict__ b1v,
                  const float* __restrict__ w2v,
                  const float* __restrict__ b2v,
                  float* __restrict__ out, int nChunks, int n) {
    __shared__ float s_f[32];          // f at 32 Chebyshev nodes
    __shared__ float s_part[32][9];    // DCT partials, padded (stride 9)
    __shared__ float s_c[NCOEF];       // final monomial coefficients

    const int tid  = threadIdx.x;
    const int lane = tid & 31;
    const int gid    = blockIdx.x * blockDim.x + tid;
    const int warpId = gid >> 5;
    const int nWarps = (gridDim.x * blockDim.x) >> 5;

    // ---- pre-issue FIRST chunk's loads (overlap with prologue) ------------
    int chunk = warpId;
    bool valid = chunk < nChunks;
    float4 v0, v1, v2, v3;
    if (valid) {
        const float4* p = data + (chunk << 7) + lane;
        v0 = __ldcs(p);
        v1 = __ldcs(p + 32);
        v2 = __ldcs(p + 64);
        v3 = __ldcs(p + 96);
    }

    // ---- prologue phase 1: f at 32 nodes, ALL 256 threads -----------------
    {
        const int node = tid >> 3;
        const int g    = tid & 7;
        float t_node = cospif((float)(2 * node + 1) * (1.0f / 64.0f));
        float a = 0.5f + 0.5f * t_node;

        float feats[BASIS];
#pragma unroll
        for (int j = 0; j < BASIS; j++) {
            float s = 0.0f;
#pragma unroll
            for (int k = 0; k < 4; k++) {
                float d = a - basis[j * 4 + k];
                s = fmaf(d, d, s);
            }
            feats[j] = __expf(-s);           // GAMMA = 1
        }
        float v = 0.0f;
#pragma unroll
        for (int u = 0; u < 2; u++) {
            int h = g + u * 8;
            float p = b1v[h];
#pragma unroll
            for (int j = 0; j < BASIS; j++)
                p = fmaf(feats[j], w1v[j * HIDDEN + h], p);
            v = fmaf(fast_tanh(p), w2v[h], v);
        }
#pragma unroll
        for (int off = 4; off; off >>= 1)
            v += __shfl_xor_sync(0xFFFFFFFFu, v, off);
        if (g == 0) s_f[node] = v + b2v[0];
    }

    // DCT weights (independent, before sync)
    const int kk = tid >> 3;
    const int gg = tid & 7;
    float wdct[4];
#pragma unroll
    for (int u = 0; u < 4; u++) {
        int j = gg * 4 + u;
        wdct[u] = cospif((float)(kk * (2 * j + 1)) * (1.0f / 64.0f));
    }
    __syncthreads();

    // ---- prologue phase 2: partial DCT dots -------------------------------
    {
        float part = 0.0f;
#pragma unroll
        for (int u = 0; u < 4; u++)
            part = fmaf(s_f[gg * 4 + u], wdct[u], part);
        s_part[kk][gg] = part;
    }
    __syncthreads();

    // ---- prologue phase 3: warp 0 reduces, converts to monomial -----------
    if (tid < 32) {
        float e = 0.0f;
#pragma unroll
        for (int g2 = 0; g2 < 8; g2++) e += s_part[lane][g2];
        e *= (1.0f / 16.0f);
        if (lane == 0) e *= 0.5f;            // e_0 = c_0/2
        float aj = 0.0f;
#pragma unroll
        for (int k = 0; k < NCOEF; k++) {
            float ek = __shfl_sync(0xFFFFFFFFu, e, k);
            aj = fmaf(ek, c_T[k][lane < NCOEF ? lane : 0], aj);
        }
        if (lane < NCOEF) s_c[lane] = aj;
    }
    __syncthreads();

    // scalar coefficient registers (12 regs; pairs packed per-iteration)
    float cs[NCOEF];
#pragma unroll
    for (int k = 0; k < NCOEF; k++) cs[k] = s_c[k];

    const float w0 = conv_w[0], w1 = conv_w[1];
    const float w2 = conv_w[2], w3 = conv_w[3];
    const float bb = conv_b[0];

    // ---- pipelined main loop ----------------------------------------------
    while (valid) {
        // consume loaded data -> t values (frees v registers early)
        float l0 = fmaf(v0.x, w0, fmaf(v0.y, w1, fmaf(v0.z, w2, fmaf(v0.w, w3, bb))));
        float l1 = fmaf(v1.x, w0, fmaf(v1.y, w1, fmaf(v1.z, w2, fmaf(v1.w, w3, bb))));
        float l2 = fmaf(v2.x, w0, fmaf(v2.y, w1, fmaf(v2.z, w2, fmaf(v2.w, w3, bb))));
        float l3 = fmaf(v3.x, w0, fmaf(v3.y, w1, fmaf(v3.z, w2, fmaf(v3.w, w3, bb))));
        float t0 = fast_tanh(0.5f * l0);
        float t1 = fast_tanh(0.5f * l1);
        float t2 = fast_tanh(0.5f * l2);
        float t3 = fast_tanh(0.5f * l3);

        const int base = (chunk << 7) + lane;

        // issue NEXT chunk's loads before the Horner chain + stores
        chunk += nWarps;
        valid = chunk < nChunks;
        if (valid) {
            const float4* p = data + (chunk << 7) + lane;
            v0 = __ldcs(p);
            v1 = __ldcs(p + 32);
            v2 = __ldcs(p + 64);
            v3 = __ldcs(p + 96);
        }

        unsigned long long tA, tB;
        PACK2(tA, t0, t1);
        PACK2(tB, t2, t3);

        // Horner, two f32x2 chains; coefficient pair packed once per level
        unsigned long long ck2;
        PACK2(ck2, cs[NCOEF - 1], cs[NCOEF - 1]);
        unsigned long long hA = ck2, hB = ck2;
#pragma unroll
        for (int k = NCOEF - 2; k >= 0; k--) {
            PACK2(ck2, cs[k], cs[k]);
            FMA2(hA, tA, hA, ck2);
            FMA2(hB, tB, hB, ck2);
        }

        float r0, r1, r2, r3;
        UNPACK2(r0, r1, hA);
        UNPACK2(r2, r3, hB);
        float* o = out + base;
        __stcs(o,      r0);
        __stcs(o + 32, r1);
        __stcs(o + 64, r2);
        __stcs(o + 96, r3);
    }

    // defensive tail for n % 128 != 0 (empty for N = 2^23)
    for (int k = (nChunks << 7) + gid; k < n; k += gridDim.x * blockDim.x) {
        float4 v = data[k];
        float l = fmaf(v.x, w0, fmaf(v.y, w1, fmaf(v.z, w2, fmaf(v.w, w3, bb))));
        float t = fast_tanh(0.5f * l);
        float h = cs[NCOEF - 1];
#pragma unroll
        for (int q = NCOEF - 2; q >= 0; q--)
            h = fmaf(t, h, cs[q]);
        out[k] = h;
    }
}

extern "C" void kernel_launch(void* const* d_in, const int* in_sizes, int n_in,
                              void* d_out, int out_size) {
    const float* data   = (const float*)d_in[0];   // [N, 2, 2]
    const float* conv_w = (const float*)d_in[1];   // [2, 2]
    const float* conv_b = (const float*)d_in[2];   // [1]
    const float* basis  = (const float*)d_in[3];   // [8, 4]
    const float* w1     = (const float*)d_in[4];   // [8, 16]
    const float* b1     = (const float*)d_in[5];   // [16]
    const float* w2     = (const float*)d_in[6];   // [16, 1]
    const float* b2     = (const float*)d_in[7];   // [1]

    const int n       = in_sizes[0] / 4;   // patches
    const int nChunks = n >> 7;            // 128-patch warp chunks

    // single launch: 912 blocks = exactly 6 CTAs/SM x 152 SMs
    hybridconv_kernel<<<912, 256>>>(
        (const float4*)data, conv_w, conv_b, basis, w1, b1, w2, b2,
        (float*)d_out, nChunks, n);
}